// round 13
// baseline (speedup 1.0000x reference)
#include <cuda_runtime.h>
#include <math.h>
#include <cstdint>

#define ADAPTERS 40
#define CAPS 3
#define CLASS_DIM 200
#define IN_CH 600
#define BATCH 256
#define DHID 768
#define NFUSED (CAPS * CLASS_DIM)  // 600

// Scratch (static device arrays -- no allocation at runtime)
__device__ float g_xT[ADAPTERS * IN_CH * BATCH];             // [k][c][b], tf32-rounded
__device__ float g_BT[ADAPTERS * CAPS * CLASS_DIM * IN_CH];  // [kn][d][c], tf32-rounded
__device__ float g_P[CAPS * ADAPTERS * BATCH * CLASS_DIM];   // [n][k][b][d]
__device__ float g_V[CAPS * BATCH * CLASS_DIM];              // [n][b][d] flat

// ---------------------------------------------------------------------------
// Software RNE rounding to tf32 bit pattern (low 13 mantissa bits zero).
// The sm_103 mma.sync tf32 fallback REQUIRES tf32-clean inputs (R11: raw fp32
// bits -> 3.5e-2 error; pre-cleaned -> ~3e-4 floor).
// ---------------------------------------------------------------------------
__device__ __forceinline__ float tf32_rne(float v) {
    uint32_t u = __float_as_uint(v);
    uint32_t r = (u + 0xFFFu + ((u >> 13) & 1u)) & 0xFFFFE000u;
    return __uint_as_float(r);
}

__device__ __forceinline__ void mma_tf32(float* c, const uint32_t a0, const uint32_t a1,
                                         const uint32_t a2, const uint32_t a3,
                                         const uint32_t b0, const uint32_t b1) {
    asm volatile(
        "mma.sync.aligned.m16n8k8.row.col.f32.tf32.tf32.f32 "
        "{%0,%1,%2,%3}, {%4,%5,%6,%7}, {%8,%9}, {%0,%1,%2,%3};"
        : "+f"(c[0]), "+f"(c[1]), "+f"(c[2]), "+f"(c[3])
        : "r"(a0), "r"(a1), "r"(a2), "r"(a3), "r"(b0), "r"(b1));
}

// ---------------------------------------------------------------------------
// Kernel 0a: transpose x (b,k,c) -> xT (k,c,b), tf32-rounded on the way out
// ---------------------------------------------------------------------------
__global__ void k_transpose(const float* __restrict__ x, const int* __restrict__ tptr) {
    int k = blockIdx.x;
    if (k > *tptr) return;
    __shared__ float tile[32][33];
    int c0 = blockIdx.y * 32;
    int b0 = blockIdx.z * 32;
    int tx = threadIdx.x, ty = threadIdx.y;  // (32, 8)
#pragma unroll
    for (int i = 0; i < 4; i++) {
        int b = b0 + ty + i * 8;
        int c = c0 + tx;
        float v = 0.f;
        if (c < IN_CH) v = x[((size_t)b * ADAPTERS + k) * IN_CH + c];
        tile[ty + i * 8][tx] = v;
    }
    __syncthreads();
#pragma unroll
    for (int i = 0; i < 4; i++) {
        int c = c0 + ty + i * 8;
        int b = b0 + tx;
        if (c < IN_CH)
            g_xT[((size_t)k * IN_CH + c) * BATCH + b] = tf32_rne(tile[tx][ty + i * 8]);
    }
}

// ---------------------------------------------------------------------------
// Kernel 0b: B transpose: rw[kn] (600c x 200d) -> g_BT[kn] (200d x 600c),
// tf32-rounded on the way out
// ---------------------------------------------------------------------------
__global__ void k_btrans(const float* __restrict__ rw, const int* __restrict__ tptr) {
    int kn = blockIdx.x;
    if (kn / 3 > *tptr) return;
    __shared__ float tile[32][33];
    int c0 = blockIdx.y * 32, d0 = blockIdx.z * 32;
    int tx = threadIdx.x, ty = threadIdx.y;  // (32,8)
#pragma unroll
    for (int i = 0; i < 4; i++) {
        int c = c0 + ty + i * 8, d = d0 + tx;
        float v = 0.f;
        if (c < IN_CH && d < CLASS_DIM) v = rw[((size_t)kn * IN_CH + c) * CLASS_DIM + d];
        tile[ty + i * 8][tx] = v;
    }
    __syncthreads();
#pragma unroll
    for (int i = 0; i < 4; i++) {
        int d = d0 + ty + i * 8, c = c0 + tx;
        if (d < CLASS_DIM && c < IN_CH)
            g_BT[((size_t)kn * CLASS_DIM + d) * IN_CH + c] = tf32_rne(tile[tx][ty + i * 8]);
    }
}

// ---------------------------------------------------------------------------
// Kernel 1: priors GEMM, single-pass tf32 mma on pre-rounded inputs (R12).
// Per CTA (k<=t, mhalf, nblock): C[128x64] = A[128x600] @ B[600x64].
// ---------------------------------------------------------------------------
#define PITCHA 136
#define PITCHB 12
#define AWORDS (8 * PITCHA)   // 1088
#define BWORDS (64 * PITCHB)  // 768
#define NSTEP (IN_CH / 8)     // 75

__global__ __launch_bounds__(128) void k_gemm_mma(const int* __restrict__ tptr) {
    int k = blockIdx.z;
    if (k > *tptr) return;
    int b0 = blockIdx.x * 128;
    int g0 = blockIdx.y * 64;

    __shared__ uint32_t S[2 * AWORDS + 2 * BWORDS];  // ~14.8 KB

    int tid = threadIdx.x;
    int lane = tid & 31;
    int wid = tid >> 5;
    int mw = wid & 1, nw = wid >> 1;
    int g = lane >> 2, tg = lane & 3;

    int arow = tid >> 5;
    int acol = (tid & 31) * 4;
    const float* ax = g_xT + ((size_t)k * IN_CH + arow) * BATCH + b0 + acol;

    int brow = tid >> 1, bcoff = (tid & 1) * 4;
    int gn = g0 + brow;
    bool bval = gn < NFUSED;
    int nr = bval ? (gn / CLASS_DIM) : 0;
    int dr = bval ? (gn - nr * CLASS_DIM) : 0;
    const float* bx = g_BT + ((size_t)(k * CAPS + nr) * CLASS_DIM + dr) * IN_CH + bcoff;

    float acc[4][4][4];
#pragma unroll
    for (int i = 0; i < 4; i++)
#pragma unroll
        for (int j = 0; j < 4; j++)
#pragma unroll
            for (int q = 0; q < 4; q++) acc[i][j][q] = 0.f;

    uint4 va0 = *reinterpret_cast<const uint4*>(ax);
    uint4 va1 = *reinterpret_cast<const uint4*>(ax + 4 * BATCH);
    uint4 vb = make_uint4(0, 0, 0, 0);
    if (bval) vb = *reinterpret_cast<const uint4*>(bx);

    {
        int ai = arow * PITCHA + acol, bi = brow * PITCHB + bcoff;
        *reinterpret_cast<uint4*>(&S[ai]) = va0;
        *reinterpret_cast<uint4*>(&S[(arow + 4) * PITCHA + acol]) = va1;
        *reinterpret_cast<uint4*>(&S[2 * AWORDS + bi]) = vb;
    }

    for (int ct = 0; ct < NSTEP; ct++) {
        __syncthreads();
        bool more = (ct + 1 < NSTEP);
        if (more) {
            int c = (ct + 1) * 8;
            va0 = *reinterpret_cast<const uint4*>(ax + (size_t)c * BATCH);
            va1 = *reinterpret_cast<const uint4*>(ax + (size_t)(c + 4) * BATCH);
            if (bval) vb = *reinterpret_cast<const uint4*>(bx + c);
        }

        int abuf = (ct & 1) * AWORDS;
        int bbuf = 2 * AWORDS + (ct & 1) * BWORDS;

        uint32_t ah0[4], ah1[4], ah2[4], ah3[4];
#pragma unroll
        for (int i = 0; i < 4; i++) {
            int m = mw * 64 + i * 16 + g;
            ah0[i] = S[abuf + tg * PITCHA + m];
            ah1[i] = S[abuf + tg * PITCHA + m + 8];
            ah2[i] = S[abuf + (tg + 4) * PITCHA + m];
            ah3[i] = S[abuf + (tg + 4) * PITCHA + m + 8];
        }
        uint32_t bh0[4], bh1[4];
#pragma unroll
        for (int j = 0; j < 4; j++) {
            int r = nw * 32 + j * 8 + g;
            bh0[j] = S[bbuf + r * PITCHB + tg];
            bh1[j] = S[bbuf + r * PITCHB + tg + 4];
        }

#pragma unroll
        for (int i = 0; i < 4; i++)
#pragma unroll
            for (int j = 0; j < 4; j++)
                mma_tf32(acc[i][j], ah0[i], ah1[i], ah2[i], ah3[i], bh0[j], bh1[j]);

        if (more) {
            int na = ((ct + 1) & 1) * AWORDS;
            int nb = 2 * AWORDS + ((ct + 1) & 1) * BWORDS;
            *reinterpret_cast<uint4*>(&S[na + arow * PITCHA + acol]) = va0;
            *reinterpret_cast<uint4*>(&S[na + (arow + 4) * PITCHA + acol]) = va1;
            *reinterpret_cast<uint4*>(&S[nb + brow * PITCHB + bcoff]) = vb;
        }
    }

#pragma unroll
    for (int j = 0; j < 4; j++) {
        int gc = g0 + nw * 32 + j * 8 + tg * 2;
        if (gc < NFUSED) {
            int n = gc / CLASS_DIM, d = gc - n * CLASS_DIM;  // gc even -> pair in-region
            float* p = g_P + ((size_t)(n * ADAPTERS + k) * BATCH) * CLASS_DIM + d;
#pragma unroll
            for (int i = 0; i < 4; i++) {
                int mr = b0 + mw * 64 + i * 16 + g;
                *reinterpret_cast<float2*>(p + (size_t)mr * CLASS_DIM) =
                    make_float2(acc[i][j][0], acc[i][j][1]);
                *reinterpret_cast<float2*>(p + (size_t)(mr + 8) * CLASS_DIM) =
                    make_float2(acc[i][j][2], acc[i][j][3]);
            }
        }
    }
}

// ---------------------------------------------------------------------------
// Kernel 2: routing v3 -- ONE WARP per (n,b), zero block barriers.
// Logits one-per-lane; softmax via xor-shuffle trees; vote[200] in 7 regs/lane
// (d = lane + 32*j); P streamed from L2 (resident after GEMM). 768 warps.
// ---------------------------------------------------------------------------
__global__ __launch_bounds__(128) void k_route(const int* __restrict__ tptr,
                                               const float* __restrict__ tsv) {
    int t = *tptr;
    int kc = t + 1;
    int w = blockIdx.x * 4 + (threadIdx.x >> 5);  // 0..767
    int lane = threadIdx.x & 31;
    int n = w >> 8;       // w / 256
    int b = w & 255;      // w % 256

    const float* Pb = g_P + ((size_t)(n * ADAPTERS) * BATCH + b) * CLASS_DIM;

    // lane-local logit state (lane k holds adapter k; only k < kc active)
    float tsv_l = 0.f, mask_l = -10000.f;
    if (lane < kc) {
        float tv = tsv[t * ADAPTERS + lane];
        tsv_l = tv;
        mask_l = (tv == 0.f) ? -10000.f : 0.f;
    }
    float l = 0.f;
    float vote[7];

    for (int it = 0; it < 3; it++) {
        // warp softmax over lanes < kc
        float leff = (lane < kc) ? fmaf(l, tsv_l, mask_l) : -3.0e38f;
        float mx = leff;
#pragma unroll
        for (int o = 16; o > 0; o >>= 1) mx = fmaxf(mx, __shfl_xor_sync(0xffffffff, mx, o));
        float e = (lane < kc) ? expf(leff - mx) : 0.f;
        float sm = e;
#pragma unroll
        for (int o = 16; o > 0; o >>= 1) sm += __shfl_xor_sync(0xffffffff, sm, o);
        float prob = e * (1.f / sm);

        // vote[d] = sum_k prob_k * P[k][d], d = lane + 32j
#pragma unroll
        for (int j = 0; j < 7; j++) vote[j] = 0.f;
        for (int k = 0; k < kc; k++) {
            float pk = __shfl_sync(0xffffffff, prob, k);
            const float* Pk = Pb + (size_t)k * BATCH * CLASS_DIM;
#pragma unroll
            for (int j = 0; j < 7; j++) {
                int d = lane + 32 * j;
                if (d < CLASS_DIM) vote[j] = fmaf(pk, __ldg(Pk + d), vote[j]);
            }
        }
        if (it == 2) break;

        // squash coefficient
        float sq = 0.f;
#pragma unroll
        for (int j = 0; j < 7; j++) sq = fmaf(vote[j], vote[j], sq);
#pragma unroll
        for (int o = 16; o > 0; o >>= 1) sq += __shfl_xor_sync(0xffffffff, sq, o);
        float coef = sqrtf(sq) / (1.f + sq);
        float outv[7];
#pragma unroll
        for (int j = 0; j < 7; j++) outv[j] = vote[j] * coef;

        // agreement: l[k] += dot(P[k], out)
        for (int k = 0; k < kc; k++) {
            const float* Pk = Pb + (size_t)k * BATCH * CLASS_DIM;
            float p = 0.f;
#pragma unroll
            for (int j = 0; j < 7; j++) {
                int d = lane + 32 * j;
                if (d < CLASS_DIM) p = fmaf(__ldg(Pk + d), outv[j], p);
            }
#pragma unroll
            for (int o = 16; o > 0; o >>= 1) p += __shfl_xor_sync(0xffffffff, p, o);
            if (lane == k) l += p;
        }
    }

    float* Vb = g_V + ((size_t)n * BATCH + b) * CLASS_DIM;
#pragma unroll
    for (int j = 0; j < 7; j++) {
        int d = lane + 32 * j;
        if (d < CLASS_DIM) Vb[d] = vote[j];
    }
}

// ---------------------------------------------------------------------------
// Kernel 3: expansion. Register-resident gated coefficients; streaming stores.
// ---------------------------------------------------------------------------
#define EXP_SPLIT 8
#define EXP_ROWS (CLASS_DIM / EXP_SPLIT)  // 25

__global__ __launch_bounds__(192) void k_expand(const int* __restrict__ tptr,
                                                const float* __restrict__ s_ptr,
                                                const float* __restrict__ W,
                                                const float* __restrict__ bvec,
                                                const float* __restrict__ el,
                                                float* __restrict__ out) {
    __shared__ float h[CLASS_DIM * CAPS];

    int b2 = blockIdx.x;
    int d2_0 = blockIdx.y * EXP_ROWS;
    int tid = threadIdx.x;
    int t = *tptr;
    float s = s_ptr[0];

    for (int idx = tid; idx < CLASS_DIM * CAPS; idx += 192)
        h[idx] = g_V[(size_t)b2 * (CLASS_DIM * CAPS) + idx];

    int j = tid * 4;
    float4 e4 = *reinterpret_cast<const float4*>(el + (size_t)t * DHID + j);
    float4 b4 = *reinterpret_cast<const float4*>(bvec + j);
    float g0 = 1.f / (1.f + expf(-s * e4.x));
    float g1 = 1.f / (1.f + expf(-s * e4.y));
    float g2 = 1.f / (1.f + expf(-s * e4.z));
    float g3 = 1.f / (1.f + expf(-s * e4.w));
    float4 w0 = *reinterpret_cast<const float4*>(W + j * 3);
    float4 w1 = *reinterpret_cast<const float4*>(W + j * 3 + 4);
    float4 w2 = *reinterpret_cast<const float4*>(W + j * 3 + 8);
    float4 c0 = make_float4(w0.x * g0, w0.y * g0, w0.z * g0, b4.x * g0);
    float4 c1 = make_float4(w0.w * g1, w1.x * g1, w1.y * g1, b4.y * g1);
    float4 c2 = make_float4(w1.z * g2, w1.w * g2, w2.x * g2, b4.z * g2);
    float4 c3 = make_float4(w2.y * g3, w2.z * g3, w2.w * g3, b4.w * g3);
    __syncthreads();

    float* ob = out + (size_t)b2 * CLASS_DIM * DHID + (size_t)d2_0 * DHID + j;
    const float* hp = h + d2_0 * 3;
#pragma unroll 5
    for (int r = 0; r < EXP_ROWS; r++) {
        float h0 = hp[0], h1 = hp[1], h2 = hp[2];
        hp += 3;
        float4 o;
        o.x = fmaf(h0, c0.x, fmaf(h1, c0.y, fmaf(h2, c0.z, c0.w)));
        o.y = fmaf(h0, c1.x, fmaf(h1, c1.y, fmaf(h2, c1.z, c1.w)));
        o.z = fmaf(h0, c2.x, fmaf(h1, c2.y, fmaf(h2, c2.z, c2.w)));
        o.w = fmaf(h0, c3.x, fmaf(h1, c3.y, fmaf(h2, c3.z, c3.w)));
        __stcs(reinterpret_cast<float4*>(ob), o);
        ob += DHID;
    }
}

// ---------------------------------------------------------------------------
extern "C" void kernel_launch(void* const* d_in, const int* in_sizes, int n_in,
                              void* d_out, int out_size) {
    const int* t = (const int*)d_in[0];
    const float* x = (const float*)d_in[1];
    const float* s = (const float*)d_in[2];
    const float* rw = (const float*)d_in[3];
    const float* W = (const float*)d_in[4];
    const float* bb = (const float*)d_in[5];
    const float* el = (const float*)d_in[6];
    const float* tsv = (const float*)d_in[7];
    float* out = (float*)d_out;

    k_transpose<<<dim3(ADAPTERS, (IN_CH + 31) / 32, BATCH / 32), dim3(32, 8)>>>(x, t);
    k_btrans<<<dim3(ADAPTERS * CAPS, (IN_CH + 31) / 32, (CLASS_DIM + 31) / 32), dim3(32, 8)>>>(rw, t);
    k_gemm_mma<<<dim3(2, (NFUSED + 63) / 64, ADAPTERS), 128>>>(t);
    k_route<<<dim3(CAPS * BATCH / 4), 128>>>(t, tsv);
    k_expand<<<dim3(BATCH, EXP_SPLIT), 192>>>(t, s, W, bb, el, out);
}

// round 14
// speedup vs baseline: 1.2662x; 1.2662x over previous
#include <cuda_runtime.h>
#include <math.h>
#include <cstdint>

#define ADAPTERS 40
#define CAPS 3
#define CLASS_DIM 200
#define IN_CH 600
#define BATCH 256
#define DHID 768
#define NFUSED (CAPS * CLASS_DIM)  // 600

// Scratch (static device arrays -- no allocation at runtime)
__device__ float g_xT[ADAPTERS * IN_CH * BATCH];             // [k][c][b], tf32-rounded
__device__ float g_P[CAPS * ADAPTERS * BATCH * CLASS_DIM];   // [n][k][b][d]
__device__ float g_V[CAPS * BATCH * CLASS_DIM];              // [n][b][d] flat

// ---------------------------------------------------------------------------
// Software RNE rounding to tf32 bit pattern (low 13 mantissa bits zero).
// The sm_103 mma.sync tf32 fallback REQUIRES tf32-clean inputs (R11: raw fp32
// bits -> 3.5e-2 error; pre-cleaned -> ~3e-4 floor).
// ---------------------------------------------------------------------------
__device__ __forceinline__ uint32_t tf32_rne_u(uint32_t u) {
    return (u + 0xFFFu + ((u >> 13) & 1u)) & 0xFFFFE000u;
}
__device__ __forceinline__ float tf32_rne(float v) {
    return __uint_as_float(tf32_rne_u(__float_as_uint(v)));
}

__device__ __forceinline__ void mma_tf32(float* c, const uint32_t a0, const uint32_t a1,
                                         const uint32_t a2, const uint32_t a3,
                                         const uint32_t b0, const uint32_t b1) {
    asm volatile(
        "mma.sync.aligned.m16n8k8.row.col.f32.tf32.tf32.f32 "
        "{%0,%1,%2,%3}, {%4,%5,%6,%7}, {%8,%9}, {%0,%1,%2,%3};"
        : "+f"(c[0]), "+f"(c[1]), "+f"(c[2]), "+f"(c[3])
        : "r"(a0), "r"(a1), "r"(a2), "r"(a3), "r"(b0), "r"(b1));
}

// ---------------------------------------------------------------------------
// Kernel 0: transpose x (b,k,c) -> xT (k,c,b), tf32-rounded on the way out
// ---------------------------------------------------------------------------
__global__ void k_transpose(const float* __restrict__ x, const int* __restrict__ tptr) {
    int k = blockIdx.x;
    if (k > *tptr) return;
    __shared__ float tile[32][33];
    int c0 = blockIdx.y * 32;
    int b0 = blockIdx.z * 32;
    int tx = threadIdx.x, ty = threadIdx.y;  // (32, 8)
#pragma unroll
    for (int i = 0; i < 4; i++) {
        int b = b0 + ty + i * 8;
        int c = c0 + tx;
        float v = 0.f;
        if (c < IN_CH) v = x[((size_t)b * ADAPTERS + k) * IN_CH + c];
        tile[ty + i * 8][tx] = v;
    }
    __syncthreads();
#pragma unroll
    for (int i = 0; i < 4; i++) {
        int c = c0 + ty + i * 8;
        int b = b0 + tx;
        if (c < IN_CH)
            g_xT[((size_t)k * IN_CH + c) * BATCH + b] = tf32_rne(tile[tx][ty + i * 8]);
    }
}

// ---------------------------------------------------------------------------
// Kernel 1: priors GEMM, single-pass tf32 mma. B staged DIRECTLY from rw
// (d contiguous -> coalesced), tf32-rounded at STS time (ALU pipe is idle).
// Per CTA (k<=t, mhalf, nblock): C[128x64] = A[128x600] @ B[600x64].
// A smem [c][b] pitch 136; B smem [c][d] pitch 72 -- fragment banks
// 8*tg+g (+8j) all distinct; STS phases conflict-free. Double-buffered.
// ---------------------------------------------------------------------------
#define PITCHA 136
#define PITCHB 72
#define AWORDS (8 * PITCHA)   // 1088
#define BWORDS (8 * PITCHB)   // 576
#define NSTEP (IN_CH / 8)     // 75

__global__ __launch_bounds__(128) void k_gemm_mma(const float* __restrict__ rw,
                                                  const int* __restrict__ tptr) {
    int k = blockIdx.z;
    if (k > *tptr) return;
    int b0 = blockIdx.x * 128;
    int g0 = blockIdx.y * 64;

    __shared__ uint32_t S[2 * AWORDS + 2 * BWORDS];  // ~13.3 KB

    int tid = threadIdx.x;
    int lane = tid & 31;
    int wid = tid >> 5;
    int mw = wid & 1, nw = wid >> 1;
    int g = lane >> 2, tg = lane & 3;

    // A staging: 8 c-rows x 128 b, from g_xT (coalesced, pre-rounded)
    int arow = tid >> 5;          // 0..3 (+4)
    int acol = (tid & 31) * 4;    // 0..124
    const float* ax = g_xT + ((size_t)k * IN_CH + arow) * BATCH + b0 + acol;

    // B staging: 8 c-rows x 64 fused-n cols, direct from rw (d contiguous)
    int crow = tid >> 4;          // 0..7
    int bcol = (tid & 15) * 4;    // 0..60
    int gn = g0 + bcol;
    bool bval = gn < NFUSED;
    int nr = bval ? (gn / CLASS_DIM) : 0;
    int dr = bval ? (gn - nr * CLASS_DIM) : 0;
    const float* bx = rw + (((size_t)(k * CAPS + nr)) * IN_CH + crow) * CLASS_DIM + dr;

    float acc[4][4][4];
#pragma unroll
    for (int i = 0; i < 4; i++)
#pragma unroll
        for (int j = 0; j < 4; j++)
#pragma unroll
            for (int q = 0; q < 4; q++) acc[i][j][q] = 0.f;

    // Prologue: k-step 0
    uint4 va0 = *reinterpret_cast<const uint4*>(ax);
    uint4 va1 = *reinterpret_cast<const uint4*>(ax + 4 * BATCH);
    uint4 vb = make_uint4(0, 0, 0, 0);
    if (bval) vb = *reinterpret_cast<const uint4*>(bx);

    {
        int ai = arow * PITCHA + acol;
        *reinterpret_cast<uint4*>(&S[ai]) = va0;
        *reinterpret_cast<uint4*>(&S[(arow + 4) * PITCHA + acol]) = va1;
        uint4 r;
        r.x = tf32_rne_u(vb.x); r.y = tf32_rne_u(vb.y);
        r.z = tf32_rne_u(vb.z); r.w = tf32_rne_u(vb.w);
        *reinterpret_cast<uint4*>(&S[2 * AWORDS + crow * PITCHB + bcol]) = r;
    }

    for (int ct = 0; ct < NSTEP; ct++) {
        __syncthreads();
        bool more = (ct + 1 < NSTEP);
        if (more) {
            int c = (ct + 1) * 8;
            va0 = *reinterpret_cast<const uint4*>(ax + (size_t)c * BATCH);
            va1 = *reinterpret_cast<const uint4*>(ax + (size_t)(c + 4) * BATCH);
            if (bval) vb = *reinterpret_cast<const uint4*>(bx + (size_t)c * CLASS_DIM);
        }

        int abuf = (ct & 1) * AWORDS;
        int bbuf = 2 * AWORDS + (ct & 1) * BWORDS;

        // A fragments: a0=A[m=g][c=tg], a1=A[g+8][tg], a2=A[g][tg+4], a3=A[g+8][tg+4]
        uint32_t ah0[4], ah1[4], ah2[4], ah3[4];
#pragma unroll
        for (int i = 0; i < 4; i++) {
            int m = mw * 64 + i * 16 + g;
            ah0[i] = S[abuf + tg * PITCHA + m];
            ah1[i] = S[abuf + tg * PITCHA + m + 8];
            ah2[i] = S[abuf + (tg + 4) * PITCHA + m];
            ah3[i] = S[abuf + (tg + 4) * PITCHA + m + 8];
        }
        // B fragments from [c][n] tile: b0=B[c=tg][n=r], b1=B[c=tg+4][n=r]
        uint32_t bh0[4], bh1[4];
#pragma unroll
        for (int j = 0; j < 4; j++) {
            int r = nw * 32 + j * 8 + g;
            bh0[j] = S[bbuf + tg * PITCHB + r];
            bh1[j] = S[bbuf + (tg + 4) * PITCHB + r];
        }

#pragma unroll
        for (int i = 0; i < 4; i++)
#pragma unroll
            for (int j = 0; j < 4; j++)
                mma_tf32(acc[i][j], ah0[i], ah1[i], ah2[i], ah3[i], bh0[j], bh1[j]);

        if (more) {
            int na = ((ct + 1) & 1) * AWORDS;
            int nb = 2 * AWORDS + ((ct + 1) & 1) * BWORDS;
            *reinterpret_cast<uint4*>(&S[na + arow * PITCHA + acol]) = va0;
            *reinterpret_cast<uint4*>(&S[na + (arow + 4) * PITCHA + acol]) = va1;
            uint4 r;
            r.x = tf32_rne_u(vb.x); r.y = tf32_rne_u(vb.y);
            r.z = tf32_rne_u(vb.z); r.w = tf32_rne_u(vb.w);
            *reinterpret_cast<uint4*>(&S[nb + crow * PITCHB + bcol]) = r;
        }
    }

    // Epilogue: c0,c1 -> row g cols 2tg,2tg+1; c2,c3 -> row g+8
#pragma unroll
    for (int j = 0; j < 4; j++) {
        int gc = g0 + nw * 32 + j * 8 + tg * 2;
        if (gc < NFUSED) {
            int n = gc / CLASS_DIM, d = gc - n * CLASS_DIM;  // gc even -> pair in-region
            float* p = g_P + ((size_t)(n * ADAPTERS + k) * BATCH) * CLASS_DIM + d;
#pragma unroll
            for (int i = 0; i < 4; i++) {
                int mr = b0 + mw * 64 + i * 16 + g;
                *reinterpret_cast<float2*>(p + (size_t)mr * CLASS_DIM) =
                    make_float2(acc[i][j][0], acc[i][j][1]);
                *reinterpret_cast<float2*>(p + (size_t)(mr + 8) * CLASS_DIM) =
                    make_float2(acc[i][j][2], acc[i][j][3]);
            }
        }
    }
}

// ---------------------------------------------------------------------------
// Kernel 2: routing (R12 block version -- measured 14.4us). Only k<=t;
// parallel warp softmax; float4 smem fill.
// ---------------------------------------------------------------------------
__global__ __launch_bounds__(256) void k_route(const int* __restrict__ tptr,
                                               const float* __restrict__ tsv) {
    __shared__ float Ps[ADAPTERS][CLASS_DIM];
    __shared__ float tsvv[ADAPTERS], maskv[ADAPTERS];
    __shared__ float l[ADAPTERS], probs[ADAPTERS];
    __shared__ float vote[CLASS_DIM], outv[CLASS_DIM];
    __shared__ float coef_s;

    int b = blockIdx.x, n = blockIdx.y;
    int tid = threadIdx.x;
    int t = *tptr;
    int kc = t + 1;

    const float* Pb = g_P + ((size_t)(n * ADAPTERS) * BATCH + b) * CLASS_DIM;
    int nf4 = kc * (CLASS_DIM / 4);
    for (int q = tid; q < nf4; q += 256) {
        int k = q / (CLASS_DIM / 4);
        int r = q - k * (CLASS_DIM / 4);
        float4 v = *reinterpret_cast<const float4*>(Pb + (size_t)k * BATCH * CLASS_DIM + r * 4);
        *reinterpret_cast<float4*>(&Ps[k][r * 4]) = v;
    }
    if (tid < ADAPTERS) {
        float tv = tsv[t * ADAPTERS + tid];
        tsvv[tid] = tv;
        maskv[tid] = (tv == 0.f) ? -10000.f : 0.f;
        l[tid] = 0.f;
    }
    __syncthreads();

    int wrp = tid >> 5, lane = tid & 31;

    for (int it = 0; it < 3; it++) {
        if (tid < 32) {
            float v0 = (tid < kc) ? fmaf(l[tid], tsvv[tid], maskv[tid]) : -3.0e38f;
            float v1 = (tid + 32 < kc) ? fmaf(l[tid + 32], tsvv[tid + 32], maskv[tid + 32]) : -3.0e38f;
            float mx = fmaxf(v0, v1);
#pragma unroll
            for (int o = 16; o > 0; o >>= 1) mx = fmaxf(mx, __shfl_xor_sync(0xffffffff, mx, o));
            float e0 = (tid < kc) ? expf(v0 - mx) : 0.f;
            float e1 = (tid + 32 < kc) ? expf(v1 - mx) : 0.f;
            float sm = e0 + e1;
#pragma unroll
            for (int o = 16; o > 0; o >>= 1) sm += __shfl_xor_sync(0xffffffff, sm, o);
            float inv = 1.f / sm;
            if (tid < kc) probs[tid] = e0 * inv;
            if (tid + 32 < kc) probs[tid + 32] = e1 * inv;
        }
        __syncthreads();

        if (tid < CLASS_DIM) {
            float v = 0.f;
            for (int kk = 0; kk < kc; kk++) v = fmaf(probs[kk], Ps[kk][tid], v);
            vote[tid] = v;
        }
        __syncthreads();
        if (it == 2) break;

        if (tid < 32) {
            float p = 0.f;
            for (int d = tid; d < CLASS_DIM; d += 32) {
                float v = vote[d];
                p = fmaf(v, v, p);
            }
#pragma unroll
            for (int o = 16; o > 0; o >>= 1) p += __shfl_xor_sync(0xffffffff, p, o);
            if (tid == 0) coef_s = sqrtf(p) / (1.f + p);
        }
        __syncthreads();
        if (tid < CLASS_DIM) outv[tid] = vote[tid] * coef_s;
        __syncthreads();

        for (int kk = wrp; kk < kc; kk += 8) {
            float p = 0.f;
            for (int d = lane; d < CLASS_DIM; d += 32) p = fmaf(Ps[kk][d], outv[d], p);
#pragma unroll
            for (int o = 16; o > 0; o >>= 1) p += __shfl_xor_sync(0xffffffff, p, o);
            if (lane == 0) l[kk] += p;
        }
        __syncthreads();
    }

    if (tid < CLASS_DIM) g_V[((size_t)n * BATCH + b) * CLASS_DIM + tid] = vote[tid];
}

// ---------------------------------------------------------------------------
// Kernel 3: expansion. Register-resident gated coefficients; streaming stores.
// ---------------------------------------------------------------------------
#define EXP_SPLIT 8
#define EXP_ROWS (CLASS_DIM / EXP_SPLIT)  // 25

__global__ __launch_bounds__(192) void k_expand(const int* __restrict__ tptr,
                                                const float* __restrict__ s_ptr,
                                                const float* __restrict__ W,
                                                const float* __restrict__ bvec,
                                                const float* __restrict__ el,
                                                float* __restrict__ out) {
    __shared__ float h[CLASS_DIM * CAPS];

    int b2 = blockIdx.x;
    int d2_0 = blockIdx.y * EXP_ROWS;
    int tid = threadIdx.x;
    int t = *tptr;
    float s = s_ptr[0];

    for (int idx = tid; idx < CLASS_DIM * CAPS; idx += 192)
        h[idx] = g_V[(size_t)b2 * (CLASS_DIM * CAPS) + idx];

    int j = tid * 4;
    float4 e4 = *reinterpret_cast<const float4*>(el + (size_t)t * DHID + j);
    float4 b4 = *reinterpret_cast<const float4*>(bvec + j);
    float g0 = 1.f / (1.f + expf(-s * e4.x));
    float g1 = 1.f / (1.f + expf(-s * e4.y));
    float g2 = 1.f / (1.f + expf(-s * e4.z));
    float g3 = 1.f / (1.f + expf(-s * e4.w));
    float4 w0 = *reinterpret_cast<const float4*>(W + j * 3);
    float4 w1 = *reinterpret_cast<const float4*>(W + j * 3 + 4);
    float4 w2 = *reinterpret_cast<const float4*>(W + j * 3 + 8);
    float4 c0 = make_float4(w0.x * g0, w0.y * g0, w0.z * g0, b4.x * g0);
    float4 c1 = make_float4(w0.w * g1, w1.x * g1, w1.y * g1, b4.y * g1);
    float4 c2 = make_float4(w1.z * g2, w1.w * g2, w2.x * g2, b4.z * g2);
    float4 c3 = make_float4(w2.y * g3, w2.z * g3, w2.w * g3, b4.w * g3);
    __syncthreads();

    float* ob = out + (size_t)b2 * CLASS_DIM * DHID + (size_t)d2_0 * DHID + j;
    const float* hp = h + d2_0 * 3;
#pragma unroll 5
    for (int r = 0; r < EXP_ROWS; r++) {
        float h0 = hp[0], h1 = hp[1], h2 = hp[2];
        hp += 3;
        float4 o;
        o.x = fmaf(h0, c0.x, fmaf(h1, c0.y, fmaf(h2, c0.z, c0.w)));
        o.y = fmaf(h0, c1.x, fmaf(h1, c1.y, fmaf(h2, c1.z, c1.w)));
        o.z = fmaf(h0, c2.x, fmaf(h1, c2.y, fmaf(h2, c2.z, c2.w)));
        o.w = fmaf(h0, c3.x, fmaf(h1, c3.y, fmaf(h2, c3.z, c3.w)));
        __stcs(reinterpret_cast<float4*>(ob), o);
        ob += DHID;
    }
}

// ---------------------------------------------------------------------------
extern "C" void kernel_launch(void* const* d_in, const int* in_sizes, int n_in,
                              void* d_out, int out_size) {
    const int* t = (const int*)d_in[0];
    const float* x = (const float*)d_in[1];
    const float* s = (const float*)d_in[2];
    const float* rw = (const float*)d_in[3];
    const float* W = (const float*)d_in[4];
    const float* bb = (const float*)d_in[5];
    const float* el = (const float*)d_in[6];
    const float* tsv = (const float*)d_in[7];
    float* out = (float*)d_out;

    k_transpose<<<dim3(ADAPTERS, (IN_CH + 31) / 32, BATCH / 32), dim3(32, 8)>>>(x, t);
    k_gemm_mma<<<dim3(2, (NFUSED + 63) / 64, ADAPTERS), 128>>>(rw, t);
    k_route<<<dim3(BATCH, CAPS), 256>>>(t, tsv);
    k_expand<<<dim3(BATCH, EXP_SPLIT), 192>>>(t, s, W, bb, el, out);
}

// round 15
// speedup vs baseline: 1.7096x; 1.3502x over previous
#include <cuda_runtime.h>
#include <math.h>
#include <cstdint>

#define ADAPTERS 40
#define CAPS 3
#define CLASS_DIM 200
#define IN_CH 600
#define BATCH 256
#define DHID 768
#define NFUSED (CAPS * CLASS_DIM)  // 600

// Scratch (static device arrays -- no allocation at runtime)
__device__ float g_xT[ADAPTERS * IN_CH * BATCH];             // [k][c][b], tf32-rounded
__device__ float g_P[CAPS * ADAPTERS * BATCH * CLASS_DIM];   // [n][k][b][d]
__device__ float g_V[CAPS * BATCH * CLASS_DIM];              // [n][b][d] flat

// ---------------------------------------------------------------------------
// Software RNE rounding to tf32 bit pattern (low 13 mantissa bits zero).
// The sm_103 mma.sync tf32 fallback REQUIRES tf32-clean inputs (R11: raw fp32
// bits -> 3.5e-2 error; pre-cleaned -> ~3e-4 floor).
// ---------------------------------------------------------------------------
__device__ __forceinline__ uint32_t tf32_rne_u(uint32_t u) {
    return (u + 0xFFFu + ((u >> 13) & 1u)) & 0xFFFFE000u;
}
__device__ __forceinline__ float tf32_rne(float v) {
    return __uint_as_float(tf32_rne_u(__float_as_uint(v)));
}

__device__ __forceinline__ void mma_tf32(float* c, const uint32_t a0, const uint32_t a1,
                                         const uint32_t a2, const uint32_t a3,
                                         const uint32_t b0, const uint32_t b1) {
    asm volatile(
        "mma.sync.aligned.m16n8k8.row.col.f32.tf32.tf32.f32 "
        "{%0,%1,%2,%3}, {%4,%5,%6,%7}, {%8,%9}, {%0,%1,%2,%3};"
        : "+f"(c[0]), "+f"(c[1]), "+f"(c[2]), "+f"(c[3])
        : "r"(a0), "r"(a1), "r"(a2), "r"(a3), "r"(b0), "r"(b1));
}

// ---------------------------------------------------------------------------
// Kernel 0: transpose x (b,k,c) -> xT (k,c,b), tf32-rounded on the way out
// ---------------------------------------------------------------------------
__global__ void k_transpose(const float* __restrict__ x, const int* __restrict__ tptr) {
    int k = blockIdx.x;
    if (k > *tptr) return;
    __shared__ float tile[32][33];
    int c0 = blockIdx.y * 32;
    int b0 = blockIdx.z * 32;
    int tx = threadIdx.x, ty = threadIdx.y;  // (32, 8)
#pragma unroll
    for (int i = 0; i < 4; i++) {
        int b = b0 + ty + i * 8;
        int c = c0 + tx;
        float v = 0.f;
        if (c < IN_CH) v = x[((size_t)b * ADAPTERS + k) * IN_CH + c];
        tile[ty + i * 8][tx] = v;
    }
    __syncthreads();
#pragma unroll
    for (int i = 0; i < 4; i++) {
        int c = c0 + ty + i * 8;
        int b = b0 + tx;
        if (c < IN_CH)
            g_xT[((size_t)k * IN_CH + c) * BATCH + b] = tf32_rne(tile[tx][ty + i * 8]);
    }
}

// ---------------------------------------------------------------------------
// Kernel 1: priors GEMM, single-pass tf32 mma, BK=24 (3 k-steps per barrier).
// Per CTA (k<=t, mhalf, nblock): C[128x64] = A[128x600] @ B[600x64].
// 25 outer steps (barriers: 75 -> 25); per step each thread stages 6 A-uint4 +
// 3 B-uint4 (3x MLP). B staged directly from rw (d contiguous), tf32-rounded
// at STS. A smem [c][b] pitch 136; B smem [c][d] pitch 72; conflict-free.
// ---------------------------------------------------------------------------
#define BKC 24
#define PITCHA 136
#define PITCHB 72
#define AWORDS (BKC * PITCHA)   // 3264
#define BWORDS (BKC * PITCHB)   // 1728
#define NSTEP (IN_CH / BKC)     // 25

__global__ __launch_bounds__(128, 3) void k_gemm_mma(const float* __restrict__ rw,
                                                     const int* __restrict__ tptr) {
    int k = blockIdx.z;
    if (k > *tptr) return;
    int b0 = blockIdx.x * 128;
    int g0 = blockIdx.y * 64;

    __shared__ uint32_t S[2 * AWORDS + 2 * BWORDS];  // ~39.9 KB

    int tid = threadIdx.x;
    int lane = tid & 31;
    int wid = tid >> 5;
    int mw = wid & 1, nw = wid >> 1;
    int g = lane >> 2, tg = lane & 3;

    // A staging: 24 c-rows x 128 b, rows arow+4i (i<6), from g_xT
    int arow = tid >> 5;          // 0..3
    int acol = (tid & 31) * 4;    // 0..124
    const float* ax = g_xT + ((size_t)k * IN_CH + arow) * BATCH + b0 + acol;

    // B staging: 24 c-rows x 64 fused-n cols, rows crow+8i (i<3), from rw
    int crow = tid >> 4;          // 0..7
    int bcol = (tid & 15) * 4;    // 0..60
    int gn = g0 + bcol;
    bool bval = gn < NFUSED;
    int nr = bval ? (gn / CLASS_DIM) : 0;
    int dr = bval ? (gn - nr * CLASS_DIM) : 0;
    const float* bx = rw + (((size_t)(k * CAPS + nr)) * IN_CH + crow) * CLASS_DIM + dr;

    float acc[4][4][4];
#pragma unroll
    for (int i = 0; i < 4; i++)
#pragma unroll
        for (int j = 0; j < 4; j++)
#pragma unroll
            for (int q = 0; q < 4; q++) acc[i][j][q] = 0.f;

    uint4 va[6];
    uint4 vbv[3];
    // Prologue: chunk 0
#pragma unroll
    for (int i = 0; i < 6; i++)
        va[i] = *reinterpret_cast<const uint4*>(ax + (size_t)(4 * i) * BATCH);
#pragma unroll
    for (int i = 0; i < 3; i++) {
        vbv[i] = make_uint4(0, 0, 0, 0);
        if (bval) vbv[i] = *reinterpret_cast<const uint4*>(bx + (size_t)(8 * i) * CLASS_DIM);
    }
    {
#pragma unroll
        for (int i = 0; i < 6; i++)
            *reinterpret_cast<uint4*>(&S[(arow + 4 * i) * PITCHA + acol]) = va[i];
#pragma unroll
        for (int i = 0; i < 3; i++) {
            uint4 r;
            r.x = tf32_rne_u(vbv[i].x); r.y = tf32_rne_u(vbv[i].y);
            r.z = tf32_rne_u(vbv[i].z); r.w = tf32_rne_u(vbv[i].w);
            *reinterpret_cast<uint4*>(&S[2 * AWORDS + (crow + 8 * i) * PITCHB + bcol]) = r;
        }
    }

    for (int ct = 0; ct < NSTEP; ct++) {
        __syncthreads();
        bool more = (ct + 1 < NSTEP);
        if (more) {
            int c = (ct + 1) * BKC;
#pragma unroll
            for (int i = 0; i < 6; i++)
                va[i] = *reinterpret_cast<const uint4*>(ax + (size_t)(c + 4 * i) * BATCH);
            if (bval) {
#pragma unroll
                for (int i = 0; i < 3; i++)
                    vbv[i] = *reinterpret_cast<const uint4*>(bx + (size_t)(c + 8 * i) * CLASS_DIM);
            }
        }

        int abuf = (ct & 1) * AWORDS;
        int bbuf = 2 * AWORDS + (ct & 1) * BWORDS;

#pragma unroll
        for (int sub = 0; sub < 3; sub++) {
            int cb = sub * 8;
            // A fragments: a0=A[m=g][c=cb+tg], a1=A[g+8], a2=A[g][cb+tg+4], a3=A[g+8]
            uint32_t ah0[4], ah1[4], ah2[4], ah3[4];
#pragma unroll
            for (int i = 0; i < 4; i++) {
                int m = mw * 64 + i * 16 + g;
                ah0[i] = S[abuf + (cb + tg) * PITCHA + m];
                ah1[i] = S[abuf + (cb + tg) * PITCHA + m + 8];
                ah2[i] = S[abuf + (cb + tg + 4) * PITCHA + m];
                ah3[i] = S[abuf + (cb + tg + 4) * PITCHA + m + 8];
            }
            // B fragments from [c][n] tile: b0=B[cb+tg][n=r], b1=B[cb+tg+4][n=r]
            uint32_t bh0[4], bh1[4];
#pragma unroll
            for (int j = 0; j < 4; j++) {
                int r = nw * 32 + j * 8 + g;
                bh0[j] = S[bbuf + (cb + tg) * PITCHB + r];
                bh1[j] = S[bbuf + (cb + tg + 4) * PITCHB + r];
            }
#pragma unroll
            for (int i = 0; i < 4; i++)
#pragma unroll
                for (int j = 0; j < 4; j++)
                    mma_tf32(acc[i][j], ah0[i], ah1[i], ah2[i], ah3[i], bh0[j], bh1[j]);
        }

        if (more) {
            int na = ((ct + 1) & 1) * AWORDS;
            int nb = 2 * AWORDS + ((ct + 1) & 1) * BWORDS;
#pragma unroll
            for (int i = 0; i < 6; i++)
                *reinterpret_cast<uint4*>(&S[na + (arow + 4 * i) * PITCHA + acol]) = va[i];
#pragma unroll
            for (int i = 0; i < 3; i++) {
                uint4 r;
                r.x = tf32_rne_u(vbv[i].x); r.y = tf32_rne_u(vbv[i].y);
                r.z = tf32_rne_u(vbv[i].z); r.w = tf32_rne_u(vbv[i].w);
                *reinterpret_cast<uint4*>(&S[nb + (crow + 8 * i) * PITCHB + bcol]) = r;
            }
        }
    }

    // Epilogue: c0,c1 -> row g cols 2tg,2tg+1; c2,c3 -> row g+8
#pragma unroll
    for (int j = 0; j < 4; j++) {
        int gc = g0 + nw * 32 + j * 8 + tg * 2;
        if (gc < NFUSED) {
            int n = gc / CLASS_DIM, d = gc - n * CLASS_DIM;  // gc even -> pair in-region
            float* p = g_P + ((size_t)(n * ADAPTERS + k) * BATCH) * CLASS_DIM + d;
#pragma unroll
            for (int i = 0; i < 4; i++) {
                int mr = b0 + mw * 64 + i * 16 + g;
                *reinterpret_cast<float2*>(p + (size_t)mr * CLASS_DIM) =
                    make_float2(acc[i][j][0], acc[i][j][1]);
                *reinterpret_cast<float2*>(p + (size_t)(mr + 8) * CLASS_DIM) =
                    make_float2(acc[i][j][2], acc[i][j][3]);
            }
        }
    }
}

// ---------------------------------------------------------------------------
// Kernel 2: routing (R12 block version -- measured 14.4us). Only k<=t;
// parallel warp softmax; float4 smem fill.
// ---------------------------------------------------------------------------
__global__ __launch_bounds__(256) void k_route(const int* __restrict__ tptr,
                                               const float* __restrict__ tsv) {
    __shared__ float Ps[ADAPTERS][CLASS_DIM];
    __shared__ float tsvv[ADAPTERS], maskv[ADAPTERS];
    __shared__ float l[ADAPTERS], probs[ADAPTERS];
    __shared__ float vote[CLASS_DIM], outv[CLASS_DIM];
    __shared__ float coef_s;

    int b = blockIdx.x, n = blockIdx.y;
    int tid = threadIdx.x;
    int t = *tptr;
    int kc = t + 1;

    const float* Pb = g_P + ((size_t)(n * ADAPTERS) * BATCH + b) * CLASS_DIM;
    int nf4 = kc * (CLASS_DIM / 4);
    for (int q = tid; q < nf4; q += 256) {
        int k = q / (CLASS_DIM / 4);
        int r = q - k * (CLASS_DIM / 4);
        float4 v = *reinterpret_cast<const float4*>(Pb + (size_t)k * BATCH * CLASS_DIM + r * 4);
        *reinterpret_cast<float4*>(&Ps[k][r * 4]) = v;
    }
    if (tid < ADAPTERS) {
        float tv = tsv[t * ADAPTERS + tid];
        tsvv[tid] = tv;
        maskv[tid] = (tv == 0.f) ? -10000.f : 0.f;
        l[tid] = 0.f;
    }
    __syncthreads();

    int wrp = tid >> 5, lane = tid & 31;

    for (int it = 0; it < 3; it++) {
        if (tid < 32) {
            float v0 = (tid < kc) ? fmaf(l[tid], tsvv[tid], maskv[tid]) : -3.0e38f;
            float v1 = (tid + 32 < kc) ? fmaf(l[tid + 32], tsvv[tid + 32], maskv[tid + 32]) : -3.0e38f;
            float mx = fmaxf(v0, v1);
#pragma unroll
            for (int o = 16; o > 0; o >>= 1) mx = fmaxf(mx, __shfl_xor_sync(0xffffffff, mx, o));
            float e0 = (tid < kc) ? expf(v0 - mx) : 0.f;
            float e1 = (tid + 32 < kc) ? expf(v1 - mx) : 0.f;
            float sm = e0 + e1;
#pragma unroll
            for (int o = 16; o > 0; o >>= 1) sm += __shfl_xor_sync(0xffffffff, sm, o);
            float inv = 1.f / sm;
            if (tid < kc) probs[tid] = e0 * inv;
            if (tid + 32 < kc) probs[tid + 32] = e1 * inv;
        }
        __syncthreads();

        if (tid < CLASS_DIM) {
            float v = 0.f;
            for (int kk = 0; kk < kc; kk++) v = fmaf(probs[kk], Ps[kk][tid], v);
            vote[tid] = v;
        }
        __syncthreads();
        if (it == 2) break;

        if (tid < 32) {
            float p = 0.f;
            for (int d = tid; d < CLASS_DIM; d += 32) {
                float v = vote[d];
                p = fmaf(v, v, p);
            }
#pragma unroll
            for (int o = 16; o > 0; o >>= 1) p += __shfl_xor_sync(0xffffffff, p, o);
            if (tid == 0) coef_s = sqrtf(p) / (1.f + p);
        }
        __syncthreads();
        if (tid < CLASS_DIM) outv[tid] = vote[tid] * coef_s;
        __syncthreads();

        for (int kk = wrp; kk < kc; kk += 8) {
            float p = 0.f;
            for (int d = lane; d < CLASS_DIM; d += 32) p = fmaf(Ps[kk][d], outv[d], p);
#pragma unroll
            for (int o = 16; o > 0; o >>= 1) p += __shfl_xor_sync(0xffffffff, p, o);
            if (lane == 0) l[kk] += p;
        }
        __syncthreads();
    }

    if (tid < CLASS_DIM) g_V[((size_t)n * BATCH + b) * CLASS_DIM + tid] = vote[tid];
}

// ---------------------------------------------------------------------------
// Kernel 3: expansion. Register-resident gated coefficients; streaming stores.
// ---------------------------------------------------------------------------
#define EXP_SPLIT 8
#define EXP_ROWS (CLASS_DIM / EXP_SPLIT)  // 25

__global__ __launch_bounds__(192) void k_expand(const int* __restrict__ tptr,
                                                const float* __restrict__ s_ptr,
                                                const float* __restrict__ W,
                                                const float* __restrict__ bvec,
                                                const float* __restrict__ el,
                                                float* __restrict__ out) {
    __shared__ float h[CLASS_DIM * CAPS];

    int b2 = blockIdx.x;
    int d2_0 = blockIdx.y * EXP_ROWS;
    int tid = threadIdx.x;
    int t = *tptr;
    float s = s_ptr[0];

    for (int idx = tid; idx < CLASS_DIM * CAPS; idx += 192)
        h[idx] = g_V[(size_t)b2 * (CLASS_DIM * CAPS) + idx];

    int j = tid * 4;
    float4 e4 = *reinterpret_cast<const float4*>(el + (size_t)t * DHID + j);
    float4 b4 = *reinterpret_cast<const float4*>(bvec + j);
    float g0 = 1.f / (1.f + expf(-s * e4.x));
    float g1 = 1.f / (1.f + expf(-s * e4.y));
    float g2 = 1.f / (1.f + expf(-s * e4.z));
    float g3 = 1.f / (1.f + expf(-s * e4.w));
    float4 w0 = *reinterpret_cast<const float4*>(W + j * 3);
    float4 w1 = *reinterpret_cast<const float4*>(W + j * 3 + 4);
    float4 w2 = *reinterpret_cast<const float4*>(W + j * 3 + 8);
    float4 c0 = make_float4(w0.x * g0, w0.y * g0, w0.z * g0, b4.x * g0);
    float4 c1 = make_float4(w0.w * g1, w1.x * g1, w1.y * g1, b4.y * g1);
    float4 c2 = make_float4(w1.z * g2, w1.w * g2, w2.x * g2, b4.z * g2);
    float4 c3 = make_float4(w2.y * g3, w2.z * g3, w2.w * g3, b4.w * g3);
    __syncthreads();

    float* ob = out + (size_t)b2 * CLASS_DIM * DHID + (size_t)d2_0 * DHID + j;
    const float* hp = h + d2_0 * 3;
#pragma unroll 5
    for (int r = 0; r < EXP_ROWS; r++) {
        float h0 = hp[0], h1 = hp[1], h2 = hp[2];
        hp += 3;
        float4 o;
        o.x = fmaf(h0, c0.x, fmaf(h1, c0.y, fmaf(h2, c0.z, c0.w)));
        o.y = fmaf(h0, c1.x, fmaf(h1, c1.y, fmaf(h2, c1.z, c1.w)));
        o.z = fmaf(h0, c2.x, fmaf(h1, c2.y, fmaf(h2, c2.z, c2.w)));
        o.w = fmaf(h0, c3.x, fmaf(h1, c3.y, fmaf(h2, c3.z, c3.w)));
        __stcs(reinterpret_cast<float4*>(ob), o);
        ob += DHID;
    }
}

// ---------------------------------------------------------------------------
extern "C" void kernel_launch(void* const* d_in, const int* in_sizes, int n_in,
                              void* d_out, int out_size) {
    const int* t = (const int*)d_in[0];
    const float* x = (const float*)d_in[1];
    const float* s = (const float*)d_in[2];
    const float* rw = (const float*)d_in[3];
    const float* W = (const float*)d_in[4];
    const float* bb = (const float*)d_in[5];
    const float* el = (const float*)d_in[6];
    const float* tsv = (const float*)d_in[7];
    float* out = (float*)d_out;

    k_transpose<<<dim3(ADAPTERS, (IN_CH + 31) / 32, BATCH / 32), dim3(32, 8)>>>(x, t);
    k_gemm_mma<<<dim3(2, (NFUSED + 63) / 64, ADAPTERS), 128>>>(rw, t);
    k_route<<<dim3(BATCH, CAPS), 256>>>(t, tsv);
    k_expand<<<dim3(BATCH, EXP_SPLIT), 192>>>(t, s, W, bb, el, out);
}